// round 12
// baseline (speedup 1.0000x reference)
#include <cuda_runtime.h>
#include <math.h>
#include <stdint.h>

// Static shapes for NativeSparseCrossAttention
#define B_      2
#define N_L     128
#define D_      512
#define N_T     16384
#define D_IN    256
#define NB      256            // blocks per batch
#define BS_     64             // tokens per block
#define TOPK    16
#define RDIM    64
#define NHEAD   8
#define HD      64
#define NLAT    (B_ * N_L)     // 256

// NO __device__ globals.  Intermediates live inside d_out (per-row slots):
//   phase A: slot[g>>1][16+(g&1)*64 .. +64) = router-K vec of summary g
//   phase B: slot[r][0:16)  = top-16 block indices (int bitcast)
//   phase C: slot[r][0:512) = o row (pre-Wo)   [K4 overwrites whole slot]
//   phase D: slot[r][0:512) = final output row

// ---------------------------------------------------------------------------
// K1: block summary (mean of 64 tokens) + router-K projection -> slots.
__global__ __launch_bounds__(256) void nsca12_k1_summary(
    const float* __restrict__ bytes,
    const float* __restrict__ Wrk,    // [256 x 64]
    const float* __restrict__ brk,    // [64]
    float* __restrict__ dout)
{
    int g = blockIdx.x;                        // 0..511
    const float* base = bytes + (size_t)g * BS_ * D_IN;
    __shared__ float s[D_IN];
    int d = threadIdx.x;
    float acc = 0.f;
    #pragma unroll 8
    for (int t = 0; t < BS_; ++t) acc += base[t * D_IN + d];
    s[d] = acc * (1.0f / 64.0f);
    __syncthreads();
    if (d < RDIM) {
        float r = brk[d];
        #pragma unroll 8
        for (int k = 0; k < D_IN; ++k) r += s[k] * Wrk[k * RDIM + d];
        dout[(size_t)(g >> 1) * 512 + 16 + (g & 1) * 64 + d] = r;
    }
}

// ---------------------------------------------------------------------------
// K2: per-row router-Q + logits + top-16 -> idx into own slot [0:16).
__global__ __launch_bounds__(256) void nsca12_k2_topk(
    const float* __restrict__ latents,
    const float* __restrict__ Wrq,    // [512 x 64]
    const float* __restrict__ brq,    // [64]
    float* __restrict__ dout)
{
    int row = blockIdx.x;
    int b   = row >> 7;
    int tid = threadIdx.x;
    int w   = tid >> 5, lane = tid & 31;
    __shared__ float lat[D_];
    __shared__ float rq[RDIM];
    __shared__ float lg[NB];
    __shared__ float wv[8];
    __shared__ int   wi[8];

    lat[tid]       = latents[(size_t)row * D_ + tid];
    lat[tid + 256] = latents[(size_t)row * D_ + tid + 256];
    __syncthreads();

    {   // rq[col] = lat . Wrq[:,col] + b ;  4 partial threads per column
        int col = tid >> 2, part = tid & 3;
        const float* Wc = Wrq + col;
        float a = 0.f;
        int k0 = part * 128;
        #pragma unroll 8
        for (int k = k0; k < k0 + 128; ++k) a += lat[k] * Wc[(size_t)k * RDIM];
        a += __shfl_xor_sync(0xffffffffu, a, 1);
        a += __shfl_xor_sync(0xffffffffu, a, 2);
        if (part == 0) rq[col] = a + brq[col];
    }
    __syncthreads();

    {   int g = b * NB + tid;
        const float* rk = dout + (size_t)(g >> 1) * 512 + 16 + (g & 1) * 64;
        float a = 0.f;
        #pragma unroll 8
        for (int j = 0; j < RDIM; ++j) a += rq[j] * rk[j];
        lg[tid] = a;
    }
    __syncthreads();

    int* idx_out = (int*)dout + (size_t)row * 512;
    for (int k = 0; k < TOPK; ++k) {
        float v = lg[tid]; int id = tid;
        #pragma unroll
        for (int off = 16; off; off >>= 1) {
            float ov = __shfl_xor_sync(0xffffffffu, v, off);
            int   oi = __shfl_xor_sync(0xffffffffu, id, off);
            if (ov > v || (ov == v && oi < id)) { v = ov; id = oi; }
        }
        if (lane == 0) { wv[w] = v; wi[w] = id; }
        __syncthreads();
        if (tid == 0) {
            float bv = wv[0]; int bi = wi[0];
            #pragma unroll
            for (int j = 1; j < 8; ++j)
                if (wv[j] > bv || (wv[j] == bv && wi[j] < bi)) { bv = wv[j]; bi = wi[j]; }
            idx_out[k] = bi; lg[bi] = -INFINITY;
        }
        __syncthreads();
    }
}

// ---------------------------------------------------------------------------
// K4: fused attention, shift-free softmax, pipelined 64-token iterations.
// (unchanged — validated)
#define NS12_SMEM_FLOATS 23320
#define NS12_SMEM_BYTES  (NS12_SMEM_FLOATS * 4)

__global__ __launch_bounds__(256, 2) void nsca12_k4_attn(
    const float* __restrict__ bytes,
    const float* __restrict__ latents,
    const float* __restrict__ Wq,
    const float* __restrict__ Wk,
    const float* __restrict__ Wv,
    float* __restrict__ dout)
{
    extern __shared__ float sm[];
    float*  xsf = sm;
    float4* xs4 = (float4*)sm;
    float*  Ut  = sm + 16640;
    float4* Ut4 = (float4*)Ut;
    float*  sP  = sm + 18688;
    float*  sQ  = sm + 18688;          // alias (dead before first score)
    float*  pB  = sm + 22784;
    float4* pB4 = (float4*)pB;
    float*  sL  = sm + 23296;
    int*    sIDX= (int*)(sm + 23304);

    int row  = blockIdx.x;
    int b    = row >> 7;
    int tid  = threadIdx.x;
    int w    = tid >> 5;
    int lane = tid & 31;

    float* slot = dout + (size_t)row * 512;

    // ---- prologue: idx, latents stage, q = lat @ Wq (full row)
    if (tid < TOPK) sIDX[tid] = ((const int*)slot)[tid];
    xsf[tid]       = latents[(size_t)row * D_ + tid];
    xsf[tid + 256] = latents[(size_t)row * D_ + tid + 256];
    if (tid < 8) sL[tid] = 0.f;
    __syncthreads();

    {   float a0 = 0.f, a1 = 0.f;
        #pragma unroll 4
        for (int k = 0; k < D_; ++k) {
            float lv = xsf[k];
            a0 += lv * Wq[(size_t)k * D_ + tid];
            a1 += lv * Wq[(size_t)k * D_ + tid + 256];
        }
        sQ[tid] = a0; sQ[tid + 256] = a1;
    }
    __syncthreads();

    // ---- U[k][h] = sum_j Wk[k][h*64+j] * q[h*64+j]   (warp w = head w)
    {
        float qx = sQ[w * 64 + lane * 2];
        float qy = sQ[w * 64 + lane * 2 + 1];
        for (int d0 = 0; d0 < 256; d0 += 8) {
            float a0, a1, a2, a3, a4, a5, a6, a7;
            {
                const float* Wb = Wk + (size_t)d0 * D_ + w * 64 + lane * 2;
                float2 t;
                t = *reinterpret_cast<const float2*>(Wb + 0 * D_); a0 = t.x * qx + t.y * qy;
                t = *reinterpret_cast<const float2*>(Wb + 1 * D_); a1 = t.x * qx + t.y * qy;
                t = *reinterpret_cast<const float2*>(Wb + 2 * D_); a2 = t.x * qx + t.y * qy;
                t = *reinterpret_cast<const float2*>(Wb + 3 * D_); a3 = t.x * qx + t.y * qy;
                t = *reinterpret_cast<const float2*>(Wb + 4 * D_); a4 = t.x * qx + t.y * qy;
                t = *reinterpret_cast<const float2*>(Wb + 5 * D_); a5 = t.x * qx + t.y * qy;
                t = *reinterpret_cast<const float2*>(Wb + 6 * D_); a6 = t.x * qx + t.y * qy;
                t = *reinterpret_cast<const float2*>(Wb + 7 * D_); a7 = t.x * qx + t.y * qy;
            }
            #pragma unroll
            for (int off = 16; off; off >>= 1) {
                a0 += __shfl_xor_sync(0xffffffffu, a0, off);
                a1 += __shfl_xor_sync(0xffffffffu, a1, off);
                a2 += __shfl_xor_sync(0xffffffffu, a2, off);
                a3 += __shfl_xor_sync(0xffffffffu, a3, off);
                a4 += __shfl_xor_sync(0xffffffffu, a4, off);
                a5 += __shfl_xor_sync(0xffffffffu, a5, off);
                a6 += __shfl_xor_sync(0xffffffffu, a6, off);
                a7 += __shfl_xor_sync(0xffffffffu, a7, off);
            }
            if (lane == 0) {
                Ut[(d0 + 0) * 8 + w] = a0; Ut[(d0 + 1) * 8 + w] = a1;
                Ut[(d0 + 2) * 8 + w] = a2; Ut[(d0 + 3) * 8 + w] = a3;
                Ut[(d0 + 4) * 8 + w] = a4; Ut[(d0 + 5) * 8 + w] = a5;
                Ut[(d0 + 6) * 8 + w] = a6; Ut[(d0 + 7) * 8 + w] = a7;
            }
        }
    }

    const float4* xb = (const float4*)bytes + (size_t)(b * N_T) * 64;

    // stage tile 0 (overwrites lat staging; lat dead after q)
    {
        const float4* src = xb + (size_t)sIDX[0] * 4096;
        #pragma unroll
        for (int j = 0; j < 16; ++j) {
            int e = tid + j * 256;
            xs4[(e >> 6) * 65 + (e & 63)] = src[e];
        }
    }
    __syncthreads();

    int dq = tid & 63, tp = tid >> 6;
    float4 c0 = {0,0,0,0}, c1 = {0,0,0,0}, c2 = {0,0,0,0}, c3 = {0,0,0,0};
    float4 c4 = {0,0,0,0}, c5 = {0,0,0,0}, c6 = {0,0,0,0}, c7 = {0,0,0,0};

    // ---- mainloop: 16 iterations of 64 tokens, 2 syncs each
    for (int m = 0; m < TOPK; ++m) {
        // [A] score: warp = k-slice, lane = token (both halves, one U stream)
        {
            float sA0=0,sA1=0,sA2=0,sA3=0,sA4=0,sA5=0,sA6=0,sA7=0;
            float sB0=0,sB1=0,sB2=0,sB3=0,sB4=0,sB5=0,sB6=0,sB7=0;
            #pragma unroll
            for (int i = 0; i < 8; ++i) {
                int k4 = w * 8 + i;
                const float4* ub = Ut4 + k4 * 8;      // broadcast reads
                float4 u0 = ub[0], u1 = ub[1], u2 = ub[2], u3 = ub[3];
                float4 u4 = ub[4], u5 = ub[5], u6 = ub[6], u7 = ub[7];
                float4 xa  = xs4[lane * 65 + k4];
                float4 xbv = xs4[(lane + 32) * 65 + k4];
                sA0 += xa.x*u0.x + xa.y*u2.x + xa.z*u4.x + xa.w*u6.x;
                sA1 += xa.x*u0.y + xa.y*u2.y + xa.z*u4.y + xa.w*u6.y;
                sA2 += xa.x*u0.z + xa.y*u2.z + xa.z*u4.z + xa.w*u6.z;
                sA3 += xa.x*u0.w + xa.y*u2.w + xa.z*u4.w + xa.w*u6.w;
                sA4 += xa.x*u1.x + xa.y*u3.x + xa.z*u5.x + xa.w*u7.x;
                sA5 += xa.x*u1.y + xa.y*u3.y + xa.z*u5.y + xa.w*u7.y;
                sA6 += xa.x*u1.z + xa.y*u3.z + xa.z*u5.z + xa.w*u7.z;
                sA7 += xa.x*u1.w + xa.y*u3.w + xa.z*u5.w + xa.w*u7.w;
                sB0 += xbv.x*u0.x + xbv.y*u2.x + xbv.z*u4.x + xbv.w*u6.x;
                sB1 += xbv.x*u0.y + xbv.y*u2.y + xbv.z*u4.y + xbv.w*u6.y;
                sB2 += xbv.x*u0.z + xbv.y*u2.z + xbv.z*u4.z + xbv.w*u6.z;
                sB3 += xbv.x*u0.w + xbv.y*u2.w + xbv.z*u4.w + xbv.w*u6.w;
                sB4 += xbv.x*u1.x + xbv.y*u3.x + xbv.z*u5.x + xbv.w*u7.x;
                sB5 += xbv.x*u1.y + xbv.y*u3.y + xbv.z*u5.y + xbv.w*u7.y;
                sB6 += xbv.x*u1.z + xbv.y*u3.z + xbv.z*u5.z + xbv.w*u7.z;
                sB7 += xbv.x*u1.w + xbv.y*u3.w + xbv.z*u5.w + xbv.w*u7.w;
            }
            float* pa = sP + w * 512 + lane;          // [ks][h][t]
            pa[0*64] = sA0; pa[1*64] = sA1; pa[2*64] = sA2; pa[3*64] = sA3;
            pa[4*64] = sA4; pa[5*64] = sA5; pa[6*64] = sA6; pa[7*64] = sA7;
            float* pb = sP + w * 512 + lane + 32;
            pb[0*64] = sB0; pb[1*64] = sB1; pb[2*64] = sB2; pb[3*64] = sB3;
            pb[4*64] = sB4; pb[5*64] = sB5; pb[6*64] = sB6; pb[7*64] = sB7;
        }
        __syncthreads();                  // [B]

        // [C] stage next tile (XS free: ctx reads L2 directly)
        if (m < TOPK - 1) {
            const float4* src = xb + (size_t)sIDX[m + 1] * 4096;
            #pragma unroll
            for (int j = 0; j < 16; ++j) {
                int e = tid + j * 256;
                xs4[(e >> 6) * 65 + (e & 63)] = src[e];
            }
        }
        // [C] exp: warp w = head w, lane = token; shift-free
        {
            float ts = 0.f;
            #pragma unroll
            for (int half = 0; half < 2; ++half) {
                int t = lane + half * 32;
                const float* p = sP + w * 64 + t;     // + ks*512
                float v = p[0] + p[512] + p[1024] + p[1536]
                        + p[2048] + p[2560] + p[3072] + p[3584];
                float pe = __expf(v * 0.125f);
                pB[t * 8 + w] = pe;
                ts += pe;
            }
            #pragma unroll
            for (int off = 16; off; off >>= 1)
                ts += __shfl_xor_sync(0xffffffffu, ts, off);
            if (lane == 0) sL[w] += ts;
        }
        __syncthreads();                  // [D]

        // [E] ctx: x via coalesced LDG (each element read once), pB broadcast
        {
            const float4* src = xb + (size_t)sIDX[m] * 4096;
            int t0 = tp * 16;
            #pragma unroll 4
            for (int t = t0; t < t0 + 16; ++t) {
                float4 xv = src[t * 64 + dq];
                float4 p0 = pB4[t * 2];
                float4 p1 = pB4[t * 2 + 1];
                c0.x += p0.x*xv.x; c0.y += p0.x*xv.y; c0.z += p0.x*xv.z; c0.w += p0.x*xv.w;
                c1.x += p0.y*xv.x; c1.y += p0.y*xv.y; c1.z += p0.y*xv.z; c1.w += p0.y*xv.w;
                c2.x += p0.z*xv.x; c2.y += p0.z*xv.y; c2.z += p0.z*xv.z; c2.w += p0.z*xv.w;
                c3.x += p0.w*xv.x; c3.y += p0.w*xv.y; c3.z += p0.w*xv.z; c3.w += p0.w*xv.w;
                c4.x += p1.x*xv.x; c4.y += p1.x*xv.y; c4.z += p1.x*xv.z; c4.w += p1.x*xv.w;
                c5.x += p1.y*xv.x; c5.y += p1.y*xv.y; c5.z += p1.y*xv.z; c5.w += p1.y*xv.w;
                c6.x += p1.z*xv.x; c6.y += p1.z*xv.y; c6.z += p1.z*xv.z; c6.w += p1.z*xv.w;
                c7.x += p1.w*xv.x; c7.y += p1.w*xv.y; c7.z += p1.w*xv.z; c7.w += p1.w*xv.w;
            }
        }
    }

    // ---- epilogue: partial stores + 1/l, reduce, o = ctx @ Wv_h -> slot
    {
        float4* red4 = xs4;
        red4[(tp * 8 + 0) * 64 + dq] = c0;
        red4[(tp * 8 + 1) * 64 + dq] = c1;
        red4[(tp * 8 + 2) * 64 + dq] = c2;
        red4[(tp * 8 + 3) * 64 + dq] = c3;
        red4[(tp * 8 + 4) * 64 + dq] = c4;
        red4[(tp * 8 + 5) * 64 + dq] = c5;
        red4[(tp * 8 + 6) * 64 + dq] = c6;
        red4[(tp * 8 + 7) * 64 + dq] = c7;
    }
    if (tid < 8) sL[tid] = 1.0f / sL[tid];
    __syncthreads();

    float* ctx_s = sP;                  // [8][260]
    for (int i = tid; i < 2048; i += 256) {
        int hh = i >> 8, k = i & 255;
        float v = xsf[(0 * 8 + hh) * 256 + k] + xsf[(1 * 8 + hh) * 256 + k]
                + xsf[(2 * 8 + hh) * 256 + k] + xsf[(3 * 8 + hh) * 256 + k];
        ctx_s[hh * 260 + k] = v * sL[hh];
    }
    __syncthreads();

    {
        float a0 = 0.f, a1 = 0.f;
        const float* ch = ctx_s + w * 260;
        #pragma unroll 4
        for (int k = 0; k < 256; ++k) {
            float2 wv = *reinterpret_cast<const float2*>(
                &Wv[(size_t)k * D_ + w * 64 + lane * 2]);
            float cv = ch[k];
            a0 += cv * wv.x; a1 += cv * wv.y;
        }
        slot[w * 64 + lane * 2]     = a0;
        slot[w * 64 + lane * 2 + 1] = a1;
    }
}

// ---------------------------------------------------------------------------
// K5 (v3): out = o @ Wo, in-place.  64 blocks x 4 rows, 256 threads =
// 2 k-slices x 128 f4-chunks.  EXPLICIT 8-deep load batching (named float4
// buffer array, all 8 LDG.128 issued before first use) -> true MLP~8.
// Race-free: stages own 4 rows fully, then overwrites only them.
__global__ __launch_bounds__(256) void nsca12_k5_oproj(
    const float* __restrict__ Wo,     // [512 x 512]
    float* __restrict__ dout)
{
    int r0 = blockIdx.x * 4;
    int tid = threadIdx.x;
    int ks = tid >> 7;                  // k-slice 0/1
    int ch = tid & 127;                 // float4 column chunk
    __shared__ float os[4][512];        // 8 KB  staged o rows
    __shared__ float red[4 * 512];      // 8 KB  cross-slice partials

    {   // stage 4 rows as float4 (2048 floats = 512 f4, 2 per thread)
        const float4* src = (const float4*)(dout + (size_t)r0 * 512);
        float4* os4 = (float4*)os;
        os4[tid]       = src[tid];
        os4[tid + 256] = src[tid + 256];
    }
    __syncthreads();

    const float4* Wo4 = (const float4*)Wo;
    float4 a0 = {0,0,0,0}, a1 = {0,0,0,0}, a2 = {0,0,0,0}, a3 = {0,0,0,0};

    for (int kb = 0; kb < 512; kb += 16) {
        // batch: 8 independent LDG.128 issued back-to-back (MLP = 8)
        float4 wv[8];
        #pragma unroll
        for (int j = 0; j < 8; ++j)
            wv[j] = Wo4[(size_t)(kb + ks + 2 * j) * 128 + ch];
        #pragma unroll
        for (int j = 0; j < 8; ++j) {
            int k = kb + ks + 2 * j;
            float o0 = os[0][k], o1 = os[1][k], o2 = os[2][k], o3 = os[3][k];
            a0.x += o0 * wv[j].x; a0.y += o0 * wv[j].y; a0.z += o0 * wv[j].z; a0.w += o0 * wv[j].w;
            a1.x += o1 * wv[j].x; a1.y += o1 * wv[j].y; a1.z += o1 * wv[j].z; a1.w += o1 * wv[j].w;
            a2.x += o2 * wv[j].x; a2.y += o2 * wv[j].y; a2.z += o2 * wv[j].z; a2.w += o2 * wv[j].w;
            a3.x += o3 * wv[j].x; a3.y += o3 * wv[j].y; a3.z += o3 * wv[j].z; a3.w += o3 * wv[j].w;
        }
    }

    // cross-slice reduction via smem
    float4* red4 = (float4*)red;
    if (ks == 1) {
        red4[0 * 128 + ch] = a0;
        red4[1 * 128 + ch] = a1;
        red4[2 * 128 + ch] = a2;
        red4[3 * 128 + ch] = a3;
    }
    __syncthreads();
    if (ks == 0) {
        float4 b0 = red4[0 * 128 + ch];
        float4 b1 = red4[1 * 128 + ch];
        float4 b2 = red4[2 * 128 + ch];
        float4 b3 = red4[3 * 128 + ch];
        a0.x += b0.x; a0.y += b0.y; a0.z += b0.z; a0.w += b0.w;
        a1.x += b1.x; a1.y += b1.y; a1.z += b1.z; a1.w += b1.w;
        a2.x += b2.x; a2.y += b2.y; a2.z += b2.z; a2.w += b2.w;
        a3.x += b3.x; a3.y += b3.y; a3.z += b3.z; a3.w += b3.w;
        float4* out4 = (float4*)dout;
        out4[(size_t)(r0 + 0) * 128 + ch] = a0;
        out4[(size_t)(r0 + 1) * 128 + ch] = a1;
        out4[(size_t)(r0 + 2) * 128 + ch] = a2;
        out4[(size_t)(r0 + 3) * 128 + ch] = a3;
    }
}

// ---------------------------------------------------------------------------
extern "C" void kernel_launch(void* const* d_in, const int* in_sizes, int n_in,
                              void* d_out, int out_size)
{
    const float* latents = (const float*)d_in[0];
    const float* bytes   = (const float*)d_in[1];
    const float* rqw     = (const float*)d_in[2];
    const float* rqb     = (const float*)d_in[3];
    const float* rkw     = (const float*)d_in[4];
    const float* rkb     = (const float*)d_in[5];
    const float* Wq      = (const float*)d_in[6];
    const float* Wk      = (const float*)d_in[7];
    const float* Wv      = (const float*)d_in[8];
    const float* Wo      = (const float*)d_in[9];
    float* out = (float*)d_out;

    cudaFuncSetAttribute(nsca12_k4_attn,
                         cudaFuncAttributeMaxDynamicSharedMemorySize, NS12_SMEM_BYTES);

    nsca12_k1_summary<<<B_ * NB, 256>>>(bytes, rkw, rkb, out);
    nsca12_k2_topk<<<NLAT, 256>>>(latents, rqw, rqb, out);
    nsca12_k4_attn<<<NLAT, 256, NS12_SMEM_BYTES>>>(bytes, latents, Wq, Wk, Wv, out);
    nsca12_k5_oproj<<<64, 256>>>(Wo, out);
}

// round 14
// speedup vs baseline: 1.0325x; 1.0325x over previous
#include <cuda_runtime.h>
#include <math.h>
#include <stdint.h>

// Static shapes for NativeSparseCrossAttention
#define B_      2
#define N_L     128
#define D_      512
#define N_T     16384
#define D_IN    256
#define NB      256            // blocks per batch
#define BS_     64             // tokens per block
#define TOPK    16
#define RDIM    64
#define NHEAD   8
#define HD      64
#define NLAT    (B_ * N_L)     // 256

// NO __device__ globals.  Intermediates live inside d_out (per-row slots):
//   phase A: slot[g>>1][16+(g&1)*64 .. +64) = router-K vec of summary g
//   phase B: slot[r][0:16)  = top-16 block indices (int bitcast)
//   phase C: slot[r][0:512) = o row (pre-Wo)   [K4 overwrites whole slot]
//   phase D: slot[r][0:512) = final output row

// ---------------------------------------------------------------------------
// K1: block summary (mean of 64 tokens) + router-K projection -> slots.
__global__ __launch_bounds__(256) void nsca13_k1_summary(
    const float* __restrict__ bytes,
    const float* __restrict__ Wrk,    // [256 x 64]
    const float* __restrict__ brk,    // [64]
    float* __restrict__ dout)
{
    int g = blockIdx.x;                        // 0..511
    const float* base = bytes + (size_t)g * BS_ * D_IN;
    __shared__ float s[D_IN];
    int d = threadIdx.x;
    float acc = 0.f;
    #pragma unroll 8
    for (int t = 0; t < BS_; ++t) acc += base[t * D_IN + d];
    s[d] = acc * (1.0f / 64.0f);
    __syncthreads();
    if (d < RDIM) {
        float r = brk[d];
        #pragma unroll 8
        for (int k = 0; k < D_IN; ++k) r += s[k] * Wrk[k * RDIM + d];
        dout[(size_t)(g >> 1) * 512 + 16 + (g & 1) * 64 + d] = r;
    }
}

// ---------------------------------------------------------------------------
// K2: per-row router-Q + logits + top-16 -> idx into own slot [0:16).
__global__ __launch_bounds__(256) void nsca13_k2_topk(
    const float* __restrict__ latents,
    const float* __restrict__ Wrq,    // [512 x 64]
    const float* __restrict__ brq,    // [64]
    float* __restrict__ dout)
{
    int row = blockIdx.x;
    int b   = row >> 7;
    int tid = threadIdx.x;
    int w   = tid >> 5, lane = tid & 31;
    __shared__ float lat[D_];
    __shared__ float rq[RDIM];
    __shared__ float lg[NB];
    __shared__ float wv[8];
    __shared__ int   wi[8];

    lat[tid]       = latents[(size_t)row * D_ + tid];
    lat[tid + 256] = latents[(size_t)row * D_ + tid + 256];
    __syncthreads();

    {   // rq[col] = lat . Wrq[:,col] + b ;  4 partial threads per column
        int col = tid >> 2, part = tid & 3;
        const float* Wc = Wrq + col;
        float a = 0.f;
        int k0 = part * 128;
        #pragma unroll 8
        for (int k = k0; k < k0 + 128; ++k) a += lat[k] * Wc[(size_t)k * RDIM];
        a += __shfl_xor_sync(0xffffffffu, a, 1);
        a += __shfl_xor_sync(0xffffffffu, a, 2);
        if (part == 0) rq[col] = a + brq[col];
    }
    __syncthreads();

    {   int g = b * NB + tid;
        const float* rk = dout + (size_t)(g >> 1) * 512 + 16 + (g & 1) * 64;
        float a = 0.f;
        #pragma unroll 8
        for (int j = 0; j < RDIM; ++j) a += rq[j] * rk[j];
        lg[tid] = a;
    }
    __syncthreads();

    int* idx_out = (int*)dout + (size_t)row * 512;
    for (int k = 0; k < TOPK; ++k) {
        float v = lg[tid]; int id = tid;
        #pragma unroll
        for (int off = 16; off; off >>= 1) {
            float ov = __shfl_xor_sync(0xffffffffu, v, off);
            int   oi = __shfl_xor_sync(0xffffffffu, id, off);
            if (ov > v || (ov == v && oi < id)) { v = ov; id = oi; }
        }
        if (lane == 0) { wv[w] = v; wi[w] = id; }
        __syncthreads();
        if (tid == 0) {
            float bv = wv[0]; int bi = wi[0];
            #pragma unroll
            for (int j = 1; j < 8; ++j)
                if (wv[j] > bv || (wv[j] == bv && wi[j] < bi)) { bv = wv[j]; bi = wi[j]; }
            idx_out[k] = bi; lg[bi] = -INFINITY;
        }
        __syncthreads();
    }
}

// ---------------------------------------------------------------------------
// K4: fused attention, shift-free softmax, pipelined 64-token iterations.
// (unchanged — validated)
#define NS13_SMEM_FLOATS 23320
#define NS13_SMEM_BYTES  (NS13_SMEM_FLOATS * 4)

__global__ __launch_bounds__(256, 2) void nsca13_k4_attn(
    const float* __restrict__ bytes,
    const float* __restrict__ latents,
    const float* __restrict__ Wq,
    const float* __restrict__ Wk,
    const float* __restrict__ Wv,
    float* __restrict__ dout)
{
    extern __shared__ float sm[];
    float*  xsf = sm;
    float4* xs4 = (float4*)sm;
    float*  Ut  = sm + 16640;
    float4* Ut4 = (float4*)Ut;
    float*  sP  = sm + 18688;
    float*  sQ  = sm + 18688;          // alias (dead before first score)
    float*  pB  = sm + 22784;
    float4* pB4 = (float4*)pB;
    float*  sL  = sm + 23296;
    int*    sIDX= (int*)(sm + 23304);

    int row  = blockIdx.x;
    int b    = row >> 7;
    int tid  = threadIdx.x;
    int w    = tid >> 5;
    int lane = tid & 31;

    float* slot = dout + (size_t)row * 512;

    // ---- prologue: idx, latents stage, q = lat @ Wq (full row)
    if (tid < TOPK) sIDX[tid] = ((const int*)slot)[tid];
    xsf[tid]       = latents[(size_t)row * D_ + tid];
    xsf[tid + 256] = latents[(size_t)row * D_ + tid + 256];
    if (tid < 8) sL[tid] = 0.f;
    __syncthreads();

    {   float a0 = 0.f, a1 = 0.f;
        #pragma unroll 4
        for (int k = 0; k < D_; ++k) {
            float lv = xsf[k];
            a0 += lv * Wq[(size_t)k * D_ + tid];
            a1 += lv * Wq[(size_t)k * D_ + tid + 256];
        }
        sQ[tid] = a0; sQ[tid + 256] = a1;
    }
    __syncthreads();

    // ---- U[k][h] = sum_j Wk[k][h*64+j] * q[h*64+j]   (warp w = head w)
    {
        float qx = sQ[w * 64 + lane * 2];
        float qy = sQ[w * 64 + lane * 2 + 1];
        for (int d0 = 0; d0 < 256; d0 += 8) {
            float a0, a1, a2, a3, a4, a5, a6, a7;
            {
                const float* Wb = Wk + (size_t)d0 * D_ + w * 64 + lane * 2;
                float2 t;
                t = *reinterpret_cast<const float2*>(Wb + 0 * D_); a0 = t.x * qx + t.y * qy;
                t = *reinterpret_cast<const float2*>(Wb + 1 * D_); a1 = t.x * qx + t.y * qy;
                t = *reinterpret_cast<const float2*>(Wb + 2 * D_); a2 = t.x * qx + t.y * qy;
                t = *reinterpret_cast<const float2*>(Wb + 3 * D_); a3 = t.x * qx + t.y * qy;
                t = *reinterpret_cast<const float2*>(Wb + 4 * D_); a4 = t.x * qx + t.y * qy;
                t = *reinterpret_cast<const float2*>(Wb + 5 * D_); a5 = t.x * qx + t.y * qy;
                t = *reinterpret_cast<const float2*>(Wb + 6 * D_); a6 = t.x * qx + t.y * qy;
                t = *reinterpret_cast<const float2*>(Wb + 7 * D_); a7 = t.x * qx + t.y * qy;
            }
            #pragma unroll
            for (int off = 16; off; off >>= 1) {
                a0 += __shfl_xor_sync(0xffffffffu, a0, off);
                a1 += __shfl_xor_sync(0xffffffffu, a1, off);
                a2 += __shfl_xor_sync(0xffffffffu, a2, off);
                a3 += __shfl_xor_sync(0xffffffffu, a3, off);
                a4 += __shfl_xor_sync(0xffffffffu, a4, off);
                a5 += __shfl_xor_sync(0xffffffffu, a5, off);
                a6 += __shfl_xor_sync(0xffffffffu, a6, off);
                a7 += __shfl_xor_sync(0xffffffffu, a7, off);
            }
            if (lane == 0) {
                Ut[(d0 + 0) * 8 + w] = a0; Ut[(d0 + 1) * 8 + w] = a1;
                Ut[(d0 + 2) * 8 + w] = a2; Ut[(d0 + 3) * 8 + w] = a3;
                Ut[(d0 + 4) * 8 + w] = a4; Ut[(d0 + 5) * 8 + w] = a5;
                Ut[(d0 + 6) * 8 + w] = a6; Ut[(d0 + 7) * 8 + w] = a7;
            }
        }
    }

    const float4* xb = (const float4*)bytes + (size_t)(b * N_T) * 64;

    // stage tile 0 (overwrites lat staging; lat dead after q)
    {
        const float4* src = xb + (size_t)sIDX[0] * 4096;
        #pragma unroll
        for (int j = 0; j < 16; ++j) {
            int e = tid + j * 256;
            xs4[(e >> 6) * 65 + (e & 63)] = src[e];
        }
    }
    __syncthreads();

    int dq = tid & 63, tp = tid >> 6;
    float4 c0 = {0,0,0,0}, c1 = {0,0,0,0}, c2 = {0,0,0,0}, c3 = {0,0,0,0};
    float4 c4 = {0,0,0,0}, c5 = {0,0,0,0}, c6 = {0,0,0,0}, c7 = {0,0,0,0};

    // ---- mainloop: 16 iterations of 64 tokens, 2 syncs each
    for (int m = 0; m < TOPK; ++m) {
        // [A] score: warp = k-slice, lane = token (both halves, one U stream)
        {
            float sA0=0,sA1=0,sA2=0,sA3=0,sA4=0,sA5=0,sA6=0,sA7=0;
            float sB0=0,sB1=0,sB2=0,sB3=0,sB4=0,sB5=0,sB6=0,sB7=0;
            #pragma unroll
            for (int i = 0; i < 8; ++i) {
                int k4 = w * 8 + i;
                const float4* ub = Ut4 + k4 * 8;      // broadcast reads
                float4 u0 = ub[0], u1 = ub[1], u2 = ub[2], u3 = ub[3];
                float4 u4 = ub[4], u5 = ub[5], u6 = ub[6], u7 = ub[7];
                float4 xa  = xs4[lane * 65 + k4];
                float4 xbv = xs4[(lane + 32) * 65 + k4];
                sA0 += xa.x*u0.x + xa.y*u2.x + xa.z*u4.x + xa.w*u6.x;
                sA1 += xa.x*u0.y + xa.y*u2.y + xa.z*u4.y + xa.w*u6.y;
                sA2 += xa.x*u0.z + xa.y*u2.z + xa.z*u4.z + xa.w*u6.z;
                sA3 += xa.x*u0.w + xa.y*u2.w + xa.z*u4.w + xa.w*u6.w;
                sA4 += xa.x*u1.x + xa.y*u3.x + xa.z*u5.x + xa.w*u7.x;
                sA5 += xa.x*u1.y + xa.y*u3.y + xa.z*u5.y + xa.w*u7.y;
                sA6 += xa.x*u1.z + xa.y*u3.z + xa.z*u5.z + xa.w*u7.z;
                sA7 += xa.x*u1.w + xa.y*u3.w + xa.z*u5.w + xa.w*u7.w;
                sB0 += xbv.x*u0.x + xbv.y*u2.x + xbv.z*u4.x + xbv.w*u6.x;
                sB1 += xbv.x*u0.y + xbv.y*u2.y + xbv.z*u4.y + xbv.w*u6.y;
                sB2 += xbv.x*u0.z + xbv.y*u2.z + xbv.z*u4.z + xbv.w*u6.z;
                sB3 += xbv.x*u0.w + xbv.y*u2.w + xbv.z*u4.w + xbv.w*u6.w;
                sB4 += xbv.x*u1.x + xbv.y*u3.x + xbv.z*u5.x + xbv.w*u7.x;
                sB5 += xbv.x*u1.y + xbv.y*u3.y + xbv.z*u5.y + xbv.w*u7.y;
                sB6 += xbv.x*u1.z + xbv.y*u3.z + xbv.z*u5.z + xbv.w*u7.z;
                sB7 += xbv.x*u1.w + xbv.y*u3.w + xbv.z*u5.w + xbv.w*u7.w;
            }
            float* pa = sP + w * 512 + lane;          // [ks][h][t]
            pa[0*64] = sA0; pa[1*64] = sA1; pa[2*64] = sA2; pa[3*64] = sA3;
            pa[4*64] = sA4; pa[5*64] = sA5; pa[6*64] = sA6; pa[7*64] = sA7;
            float* pb = sP + w * 512 + lane + 32;
            pb[0*64] = sB0; pb[1*64] = sB1; pb[2*64] = sB2; pb[3*64] = sB3;
            pb[4*64] = sB4; pb[5*64] = sB5; pb[6*64] = sB6; pb[7*64] = sB7;
        }
        __syncthreads();                  // [B]

        // [C] stage next tile (XS free: ctx reads L2 directly)
        if (m < TOPK - 1) {
            const float4* src = xb + (size_t)sIDX[m + 1] * 4096;
            #pragma unroll
            for (int j = 0; j < 16; ++j) {
                int e = tid + j * 256;
                xs4[(e >> 6) * 65 + (e & 63)] = src[e];
            }
        }
        // [C] exp: warp w = head w, lane = token; shift-free
        {
            float ts = 0.f;
            #pragma unroll
            for (int half = 0; half < 2; ++half) {
                int t = lane + half * 32;
                const float* p = sP + w * 64 + t;     // + ks*512
                float v = p[0] + p[512] + p[1024] + p[1536]
                        + p[2048] + p[2560] + p[3072] + p[3584];
                float pe = __expf(v * 0.125f);
                pB[t * 8 + w] = pe;
                ts += pe;
            }
            #pragma unroll
            for (int off = 16; off; off >>= 1)
                ts += __shfl_xor_sync(0xffffffffu, ts, off);
            if (lane == 0) sL[w] += ts;
        }
        __syncthreads();                  // [D]

        // [E] ctx: x via coalesced LDG (each element read once), pB broadcast
        {
            const float4* src = xb + (size_t)sIDX[m] * 4096;
            int t0 = tp * 16;
            #pragma unroll 4
            for (int t = t0; t < t0 + 16; ++t) {
                float4 xv = src[t * 64 + dq];
                float4 p0 = pB4[t * 2];
                float4 p1 = pB4[t * 2 + 1];
                c0.x += p0.x*xv.x; c0.y += p0.x*xv.y; c0.z += p0.x*xv.z; c0.w += p0.x*xv.w;
                c1.x += p0.y*xv.x; c1.y += p0.y*xv.y; c1.z += p0.y*xv.z; c1.w += p0.y*xv.w;
                c2.x += p0.z*xv.x; c2.y += p0.z*xv.y; c2.z += p0.z*xv.z; c2.w += p0.z*xv.w;
                c3.x += p0.w*xv.x; c3.y += p0.w*xv.y; c3.z += p0.w*xv.z; c3.w += p0.w*xv.w;
                c4.x += p1.x*xv.x; c4.y += p1.x*xv.y; c4.z += p1.x*xv.z; c4.w += p1.x*xv.w;
                c5.x += p1.y*xv.x; c5.y += p1.y*xv.y; c5.z += p1.y*xv.z; c5.w += p1.y*xv.w;
                c6.x += p1.z*xv.x; c6.y += p1.z*xv.y; c6.z += p1.z*xv.z; c6.w += p1.z*xv.w;
                c7.x += p1.w*xv.x; c7.y += p1.w*xv.y; c7.z += p1.w*xv.z; c7.w += p1.w*xv.w;
            }
        }
    }

    // ---- epilogue: partial stores + 1/l, reduce, o = ctx @ Wv_h -> slot
    {
        float4* red4 = xs4;
        red4[(tp * 8 + 0) * 64 + dq] = c0;
        red4[(tp * 8 + 1) * 64 + dq] = c1;
        red4[(tp * 8 + 2) * 64 + dq] = c2;
        red4[(tp * 8 + 3) * 64 + dq] = c3;
        red4[(tp * 8 + 4) * 64 + dq] = c4;
        red4[(tp * 8 + 5) * 64 + dq] = c5;
        red4[(tp * 8 + 6) * 64 + dq] = c6;
        red4[(tp * 8 + 7) * 64 + dq] = c7;
    }
    if (tid < 8) sL[tid] = 1.0f / sL[tid];
    __syncthreads();

    float* ctx_s = sP;                  // [8][260]
    for (int i = tid; i < 2048; i += 256) {
        int hh = i >> 8, k = i & 255;
        float v = xsf[(0 * 8 + hh) * 256 + k] + xsf[(1 * 8 + hh) * 256 + k]
                + xsf[(2 * 8 + hh) * 256 + k] + xsf[(3 * 8 + hh) * 256 + k];
        ctx_s[hh * 260 + k] = v * sL[hh];
    }
    __syncthreads();

    {
        float a0 = 0.f, a1 = 0.f;
        const float* ch = ctx_s + w * 260;
        #pragma unroll 4
        for (int k = 0; k < 256; ++k) {
            float2 wv = *reinterpret_cast<const float2*>(
                &Wv[(size_t)k * D_ + w * 64 + lane * 2]);
            float cv = ch[k];
            a0 += cv * wv.x; a1 += cv * wv.y;
        }
        slot[w * 64 + lane * 2]     = a0;
        slot[w * 64 + lane * 2 + 1] = a1;
    }
}

// ---------------------------------------------------------------------------
// K5 (v4, cp.async): out = o @ Wo, in-place.  64 blocks x 4 rows.
// Wo streamed through a 2 x 32 KB smem double buffer via cp.async (LDGSTS:
// no register load buffers -> ptxas cannot defeat the MLP).  Per chunk:
// prefetch(c+1) || compute(c).  Race-free: stages own 4 rows fully first,
// writes only them at the end.
// dyn smem floats: os @0 [4][512]; buf @2048 [2][8192]; red @18432 [2048]
#define K5_SMEM_FLOATS 20480
#define K5_SMEM_BYTES  (K5_SMEM_FLOATS * 4)

__global__ __launch_bounds__(256) void nsca13_k5_oproj(
    const float* __restrict__ Wo,     // [512 x 512]
    float* __restrict__ dout)
{
    extern __shared__ float s5[];
    float*  os   = s5;                          // [4][512]
    float4* red4 = (float4*)(s5 + 18432);       // [4][128] f4

    int r0 = blockIdx.x * 4;
    int tid = threadIdx.x;
    int ks = tid >> 7;                  // k-slice 0/1
    int ch = tid & 127;                 // float4 column chunk

    {   // stage own 4 o-rows (512 f4)
        const float4* src = (const float4*)(dout + (size_t)r0 * 512);
        float4* os4 = (float4*)os;
        os4[tid]       = src[tid];
        os4[tid + 256] = src[tid + 256];
    }

    const float4* Wo4 = (const float4*)Wo;
    uint32_t b0addr = (uint32_t)__cvta_generic_to_shared(s5 + 2048);
    uint32_t b1addr = b0addr + 8192 * 4;

    // prefetch chunk 0 (16 k-rows = 2048 f4)
    {
        #pragma unroll
        for (int j = 0; j < 8; ++j) {
            int e = tid + j * 256;
            asm volatile("cp.async.cg.shared.global [%0], [%1], 16;"
                :: "r"(b0addr + e * 16), "l"(Wo4 + e) : "memory");
        }
        asm volatile("cp.async.commit_group;" ::: "memory");
    }

    float4 a0 = {0,0,0,0}, a1 = {0,0,0,0}, a2 = {0,0,0,0}, a3 = {0,0,0,0};

    for (int c = 0; c < 32; ++c) {
        if (c + 1 < 32) {
            uint32_t dst = ((c + 1) & 1) ? b1addr : b0addr;
            const float4* g = Wo4 + (size_t)(c + 1) * 2048;
            #pragma unroll
            for (int j = 0; j < 8; ++j) {
                int e = tid + j * 256;
                asm volatile("cp.async.cg.shared.global [%0], [%1], 16;"
                    :: "r"(dst + e * 16), "l"(g + e) : "memory");
            }
            asm volatile("cp.async.commit_group;" ::: "memory");
            asm volatile("cp.async.wait_group 1;" ::: "memory");
        } else {
            asm volatile("cp.async.wait_group 0;" ::: "memory");
        }
        __syncthreads();                 // chunk c resident (also covers os stage)

        const float4* Bc = (const float4*)(s5 + 2048 + (c & 1) * 8192);
        #pragma unroll
        for (int j = 0; j < 8; ++j) {
            int kl = ks + 2 * j;                  // local k-row 0..15
            int k  = c * 16 + kl;
            float4 wv = Bc[kl * 128 + ch];
            float o0 = os[k], o1 = os[512 + k], o2 = os[1024 + k], o3 = os[1536 + k];
            a0.x += o0 * wv.x; a0.y += o0 * wv.y; a0.z += o0 * wv.z; a0.w += o0 * wv.w;
            a1.x += o1 * wv.x; a1.y += o1 * wv.y; a1.z += o1 * wv.z; a1.w += o1 * wv.w;
            a2.x += o2 * wv.x; a2.y += o2 * wv.y; a2.z += o2 * wv.z; a2.w += o2 * wv.w;
            a3.x += o3 * wv.x; a3.y += o3 * wv.y; a3.z += o3 * wv.z; a3.w += o3 * wv.w;
        }
        __syncthreads();                 // done with buf[c&1] before its re-fill
    }

    // cross-slice reduction via smem, then in-place write of own 4 rows
    if (ks == 1) {
        red4[0 * 128 + ch] = a0;
        red4[1 * 128 + ch] = a1;
        red4[2 * 128 + ch] = a2;
        red4[3 * 128 + ch] = a3;
    }
    __syncthreads();
    if (ks == 0) {
        float4 b0 = red4[0 * 128 + ch];
        float4 b1 = red4[1 * 128 + ch];
        float4 b2 = red4[2 * 128 + ch];
        float4 b3 = red4[3 * 128 + ch];
        a0.x += b0.x; a0.y += b0.y; a0.z += b0.z; a0.w += b0.w;
        a1.x += b1.x; a1.y += b1.y; a1.z += b1.z; a1.w += b1.w;
        a2.x += b2.x; a2.y += b2.y; a2.z += b2.z; a2.w += b2.w;
        a3.x += b3.x; a3.y += b3.y; a3.z += b3.z; a3.w += b3.w;
        float4* out4 = (float4*)dout;
        out4[(size_t)(r0 + 0) * 128 + ch] = a0;
        out4[(size_t)(r0 + 1) * 128 + ch] = a1;
        out4[(size_t)(r0 + 2) * 128 + ch] = a2;
        out4[(size_t)(r0 + 3) * 128 + ch] = a3;
    }
}

// ---------------------------------------------------------------------------
extern "C" void kernel_launch(void* const* d_in, const int* in_sizes, int n_in,
                              void* d_out, int out_size)
{
    const float* latents = (const float*)d_in[0];
    const float* bytes   = (const float*)d_in[1];
    const float* rqw     = (const float*)d_in[2];
    const float* rqb     = (const float*)d_in[3];
    const float* rkw     = (const float*)d_in[4];
    const float* rkb     = (const float*)d_in[5];
    const float* Wq      = (const float*)d_in[6];
    const float* Wk      = (const float*)d_in[7];
    const float* Wv      = (const float*)d_in[8];
    const float* Wo      = (const float*)d_in[9];
    float* out = (float*)d_out;

    cudaFuncSetAttribute(nsca13_k4_attn,
                         cudaFuncAttributeMaxDynamicSharedMemorySize, NS13_SMEM_BYTES);
    cudaFuncSetAttribute(nsca13_k5_oproj,
                         cudaFuncAttributeMaxDynamicSharedMemorySize, K5_SMEM_BYTES);

    nsca13_k1_summary<<<B_ * NB, 256>>>(bytes, rkw, rkb, out);
    nsca13_k2_topk<<<NLAT, 256>>>(latents, rqw, rqb, out);
    nsca13_k4_attn<<<NLAT, 256, NS13_SMEM_BYTES>>>(bytes, latents, Wq, Wk, Wv, out);
    nsca13_k5_oproj<<<64, 256, K5_SMEM_BYTES>>>(Wo, out);
}

// round 15
// speedup vs baseline: 1.0636x; 1.0302x over previous
#include <cuda_runtime.h>
#include <math.h>
#include <stdint.h>

// Static shapes for NativeSparseCrossAttention
#define B_      2
#define N_L     128
#define D_      512
#define N_T     16384
#define D_IN    256
#define NB      256            // blocks per batch
#define BS_     64             // tokens per block
#define TOPK    16
#define RDIM    64
#define NHEAD   8
#define HD      64
#define NLAT    (B_ * N_L)     // 256

// Packed fp32x2 helpers (Blackwell; PTX-only — ptxas never auto-fuses)
__device__ __forceinline__ unsigned long long pk2(float v) {
    unsigned long long r;
    asm("mov.b64 %0, {%1, %1};" : "=l"(r) : "f"(v));
    return r;
}
__device__ __forceinline__ void fma2(unsigned long long& d,
                                     unsigned long long a,
                                     unsigned long long b) {
    asm("fma.rn.f32x2 %0, %1, %2, %0;" : "+l"(d) : "l"(a), "l"(b));
}
__device__ __forceinline__ void upk2(unsigned long long v, float& lo, float& hi) {
    asm("mov.b64 {%0, %1}, %2;" : "=f"(lo), "=f"(hi) : "l"(v));
}

// NO __device__ globals.  Intermediates live inside d_out (per-row slots):
//   phase A: slot[g>>1][16+(g&1)*64 .. +64) = router-K vec of summary g
//   phase B: slot[r][0:16)  = top-16 block indices (int bitcast)
//   phase C: slot[r][0:512) = o row (pre-Wo)
//   phase D: slot[r][0:512) = final output row

// ---------------------------------------------------------------------------
// K1: block summary (mean of 64 tokens) + router-K projection -> slots.
__global__ __launch_bounds__(256) void nsca14_k1_summary(
    const float* __restrict__ bytes,
    const float* __restrict__ Wrk,
    const float* __restrict__ brk,
    float* __restrict__ dout)
{
    int g = blockIdx.x;
    const float* base = bytes + (size_t)g * BS_ * D_IN;
    __shared__ float s[D_IN];
    int d = threadIdx.x;
    float acc = 0.f;
    #pragma unroll 8
    for (int t = 0; t < BS_; ++t) acc += base[t * D_IN + d];
    s[d] = acc * (1.0f / 64.0f);
    __syncthreads();
    if (d < RDIM) {
        float r = brk[d];
        #pragma unroll 8
        for (int k = 0; k < D_IN; ++k) r += s[k] * Wrk[k * RDIM + d];
        dout[(size_t)(g >> 1) * 512 + 16 + (g & 1) * 64 + d] = r;
    }
}

// ---------------------------------------------------------------------------
// K2: per-row router-Q + logits + top-16 -> idx into own slot [0:16).
__global__ __launch_bounds__(256) void nsca14_k2_topk(
    const float* __restrict__ latents,
    const float* __restrict__ Wrq,
    const float* __restrict__ brq,
    float* __restrict__ dout)
{
    int row = blockIdx.x;
    int b   = row >> 7;
    int tid = threadIdx.x;
    int w   = tid >> 5, lane = tid & 31;
    __shared__ float lat[D_];
    __shared__ float rq[RDIM];
    __shared__ float lg[NB];
    __shared__ float wv[8];
    __shared__ int   wi[8];

    lat[tid]       = latents[(size_t)row * D_ + tid];
    lat[tid + 256] = latents[(size_t)row * D_ + tid + 256];
    __syncthreads();

    {
        int col = tid >> 2, part = tid & 3;
        const float* Wc = Wrq + col;
        float a = 0.f;
        int k0 = part * 128;
        #pragma unroll 8
        for (int k = k0; k < k0 + 128; ++k) a += lat[k] * Wc[(size_t)k * RDIM];
        a += __shfl_xor_sync(0xffffffffu, a, 1);
        a += __shfl_xor_sync(0xffffffffu, a, 2);
        if (part == 0) rq[col] = a + brq[col];
    }
    __syncthreads();

    {
        int g = b * NB + tid;
        const float* rk = dout + (size_t)(g >> 1) * 512 + 16 + (g & 1) * 64;
        float a = 0.f;
        #pragma unroll 8
        for (int j = 0; j < RDIM; ++j) a += rq[j] * rk[j];
        lg[tid] = a;
    }
    __syncthreads();

    int* idx_out = (int*)dout + (size_t)row * 512;
    for (int k = 0; k < TOPK; ++k) {
        float v = lg[tid]; int id = tid;
        #pragma unroll
        for (int off = 16; off; off >>= 1) {
            float ov = __shfl_xor_sync(0xffffffffu, v, off);
            int   oi = __shfl_xor_sync(0xffffffffu, id, off);
            if (ov > v || (ov == v && oi < id)) { v = ov; id = oi; }
        }
        if (lane == 0) { wv[w] = v; wi[w] = id; }
        __syncthreads();
        if (tid == 0) {
            float bv = wv[0]; int bi = wi[0];
            #pragma unroll
            for (int j = 1; j < 8; ++j)
                if (wv[j] > bv || (wv[j] == bv && wi[j] < bi)) { bv = wv[j]; bi = wi[j]; }
            idx_out[k] = bi; lg[bi] = -INFINITY;
        }
        __syncthreads();
    }
}

// ---------------------------------------------------------------------------
// K4: fused attention, shift-free softmax, pipelined; score & ctx inner loops
// rewritten with packed fma.rn.f32x2 (heads pairwise) — per-lane bit-identical
// fp32 math, half the FMA instruction stream.
#define NS14_SMEM_FLOATS 23320
#define NS14_SMEM_BYTES  (NS14_SMEM_FLOATS * 4)

__global__ __launch_bounds__(256, 2) void nsca14_k4_attn(
    const float* __restrict__ bytes,
    const float* __restrict__ latents,
    const float* __restrict__ Wq,
    const float* __restrict__ Wk,
    const float* __restrict__ Wv,
    float* __restrict__ dout)
{
    extern __shared__ float sm[];
    float*  xsf = sm;
    float4* xs4 = (float4*)sm;
    float*  Ut  = sm + 16640;          // [256][8]  U k-major
    float*  sP  = sm + 18688;
    float*  sQ  = sm + 18688;          // alias (dead before first score)
    float*  pB  = sm + 22784;          // [64][8]
    float*  sL  = sm + 23296;
    int*    sIDX= (int*)(sm + 23304);

    int row  = blockIdx.x;
    int b    = row >> 7;
    int tid  = threadIdx.x;
    int w    = tid >> 5;
    int lane = tid & 31;

    float* slot = dout + (size_t)row * 512;

    // ---- prologue: idx, latents stage, q = lat @ Wq (full row)
    if (tid < TOPK) sIDX[tid] = ((const int*)slot)[tid];
    xsf[tid]       = latents[(size_t)row * D_ + tid];
    xsf[tid + 256] = latents[(size_t)row * D_ + tid + 256];
    if (tid < 8) sL[tid] = 0.f;
    __syncthreads();

    {   float a0 = 0.f, a1 = 0.f;
        #pragma unroll 4
        for (int k = 0; k < D_; ++k) {
            float lv = xsf[k];
            a0 += lv * Wq[(size_t)k * D_ + tid];
            a1 += lv * Wq[(size_t)k * D_ + tid + 256];
        }
        sQ[tid] = a0; sQ[tid + 256] = a1;
    }
    __syncthreads();

    // ---- U[k][h] = sum_j Wk[k][h*64+j] * q[h*64+j]   (warp w = head w)
    {
        float qx = sQ[w * 64 + lane * 2];
        float qy = sQ[w * 64 + lane * 2 + 1];
        for (int d0 = 0; d0 < 256; d0 += 8) {
            float a0, a1, a2, a3, a4, a5, a6, a7;
            {
                const float* Wb = Wk + (size_t)d0 * D_ + w * 64 + lane * 2;
                float2 t;
                t = *reinterpret_cast<const float2*>(Wb + 0 * D_); a0 = t.x * qx + t.y * qy;
                t = *reinterpret_cast<const float2*>(Wb + 1 * D_); a1 = t.x * qx + t.y * qy;
                t = *reinterpret_cast<const float2*>(Wb + 2 * D_); a2 = t.x * qx + t.y * qy;
                t = *reinterpret_cast<const float2*>(Wb + 3 * D_); a3 = t.x * qx + t.y * qy;
                t = *reinterpret_cast<const float2*>(Wb + 4 * D_); a4 = t.x * qx + t.y * qy;
                t = *reinterpret_cast<const float2*>(Wb + 5 * D_); a5 = t.x * qx + t.y * qy;
                t = *reinterpret_cast<const float2*>(Wb + 6 * D_); a6 = t.x * qx + t.y * qy;
                t = *reinterpret_cast<const float2*>(Wb + 7 * D_); a7 = t.x * qx + t.y * qy;
            }
            #pragma unroll
            for (int off = 16; off; off >>= 1) {
                a0 += __shfl_xor_sync(0xffffffffu, a0, off);
                a1 += __shfl_xor_sync(0xffffffffu, a1, off);
                a2 += __shfl_xor_sync(0xffffffffu, a2, off);
                a3 += __shfl_xor_sync(0xffffffffu, a3, off);
                a4 += __shfl_xor_sync(0xffffffffu, a4, off);
                a5 += __shfl_xor_sync(0xffffffffu, a5, off);
                a6 += __shfl_xor_sync(0xffffffffu, a6, off);
                a7 += __shfl_xor_sync(0xffffffffu, a7, off);
            }
            if (lane == 0) {
                Ut[(d0 + 0) * 8 + w] = a0; Ut[(d0 + 1) * 8 + w] = a1;
                Ut[(d0 + 2) * 8 + w] = a2; Ut[(d0 + 3) * 8 + w] = a3;
                Ut[(d0 + 4) * 8 + w] = a4; Ut[(d0 + 5) * 8 + w] = a5;
                Ut[(d0 + 6) * 8 + w] = a6; Ut[(d0 + 7) * 8 + w] = a7;
            }
        }
    }

    const float4* xb = (const float4*)bytes + (size_t)(b * N_T) * 64;

    // stage tile 0
    {
        const float4* src = xb + (size_t)sIDX[0] * 4096;
        #pragma unroll
        for (int j = 0; j < 16; ++j) {
            int e = tid + j * 256;
            xs4[(e >> 6) * 65 + (e & 63)] = src[e];
        }
    }
    __syncthreads();

    int dq = tid & 63, tp = tid >> 6;
    // ctx accumulators: cc[hp][comp] = (head 2hp, head 2hp+1) packed fp32x2
    unsigned long long cc[4][4];
    #pragma unroll
    for (int i = 0; i < 4; ++i)
        #pragma unroll
        for (int j = 0; j < 4; ++j) cc[i][j] = 0ULL;

    // ---- mainloop: 16 iterations of 64 tokens, 2 syncs each
    for (int m = 0; m < TOPK; ++m) {
        // [A] score (f32x2): warp = k-slice, lane = token, both halves
        {
            unsigned long long sA[4] = {0ULL, 0ULL, 0ULL, 0ULL};
            unsigned long long sB[4] = {0ULL, 0ULL, 0ULL, 0ULL};
            #pragma unroll
            for (int i = 0; i < 8; ++i) {
                int k4 = w * 8 + i;
                float4 xa  = xs4[lane * 65 + k4];
                float4 xbv = xs4[(lane + 32) * 65 + k4];
                const float* urow = Ut + (k4 * 4) * 8;
                #pragma unroll
                for (int c = 0; c < 4; ++c) {
                    const unsigned long long* up =
                        (const unsigned long long*)(urow + c * 8);
                    unsigned long long u0 = up[0], u1 = up[1], u2 = up[2], u3 = up[3];
                    float xc = (c == 0) ? xa.x : (c == 1) ? xa.y : (c == 2) ? xa.z : xa.w;
                    float yc = (c == 0) ? xbv.x : (c == 1) ? xbv.y : (c == 2) ? xbv.z : xbv.w;
                    unsigned long long xc2 = pk2(xc), yc2 = pk2(yc);
                    fma2(sA[0], xc2, u0); fma2(sA[1], xc2, u1);
                    fma2(sA[2], xc2, u2); fma2(sA[3], xc2, u3);
                    fma2(sB[0], yc2, u0); fma2(sB[1], yc2, u1);
                    fma2(sB[2], yc2, u2); fma2(sB[3], yc2, u3);
                }
            }
            float* pa = sP + w * 512 + lane;          // [ks][h][t]
            float* pb = pa + 32;
            #pragma unroll
            for (int hp = 0; hp < 4; ++hp) {
                float lo, hi;
                upk2(sA[hp], lo, hi);
                pa[(2 * hp) * 64] = lo; pa[(2 * hp + 1) * 64] = hi;
                upk2(sB[hp], lo, hi);
                pb[(2 * hp) * 64] = lo; pb[(2 * hp + 1) * 64] = hi;
            }
        }
        __syncthreads();                  // [B]

        // [C] stage next tile
        if (m < TOPK - 1) {
            const float4* src = xb + (size_t)sIDX[m + 1] * 4096;
            #pragma unroll
            for (int j = 0; j < 16; ++j) {
                int e = tid + j * 256;
                xs4[(e >> 6) * 65 + (e & 63)] = src[e];
            }
        }
        // [C] exp: warp w = head w, lane = token; shift-free
        {
            float ts = 0.f;
            #pragma unroll
            for (int half = 0; half < 2; ++half) {
                int t = lane + half * 32;
                const float* p = sP + w * 64 + t;
                float v = p[0] + p[512] + p[1024] + p[1536]
                        + p[2048] + p[2560] + p[3072] + p[3584];
                float pe = __expf(v * 0.125f);
                pB[t * 8 + w] = pe;
                ts += pe;
            }
            #pragma unroll
            for (int off = 16; off; off >>= 1)
                ts += __shfl_xor_sync(0xffffffffu, ts, off);
            if (lane == 0) sL[w] += ts;
        }
        __syncthreads();                  // [D]

        // [E] ctx (f32x2): x via coalesced LDG, p head-pairs via LDS.64 bcast
        {
            const float4* src = xb + (size_t)sIDX[m] * 4096;
            int t0 = tp * 16;
            #pragma unroll 4
            for (int t = t0; t < t0 + 16; ++t) {
                float4 xv = src[t * 64 + dq];
                const unsigned long long* pp =
                    (const unsigned long long*)(pB + t * 8);
                unsigned long long p0 = pp[0], p1 = pp[1], p2 = pp[2], p3 = pp[3];
                unsigned long long vx = pk2(xv.x), vy = pk2(xv.y);
                unsigned long long vz = pk2(xv.z), vw = pk2(xv.w);
                fma2(cc[0][0], p0, vx); fma2(cc[0][1], p0, vy);
                fma2(cc[0][2], p0, vz); fma2(cc[0][3], p0, vw);
                fma2(cc[1][0], p1, vx); fma2(cc[1][1], p1, vy);
                fma2(cc[1][2], p1, vz); fma2(cc[1][3], p1, vw);
                fma2(cc[2][0], p2, vx); fma2(cc[2][1], p2, vy);
                fma2(cc[2][2], p2, vz); fma2(cc[2][3], p2, vw);
                fma2(cc[3][0], p3, vx); fma2(cc[3][1], p3, vy);
                fma2(cc[3][2], p3, vz); fma2(cc[3][3], p3, vw);
            }
        }
    }

    // ---- epilogue: unpack + partial stores, 1/l, reduce, o = ctx @ Wv_h
    {
        float4* red4 = xs4;
        #pragma unroll
        for (int hp = 0; hp < 4; ++hp) {
            float l0, h0, l1, h1, l2, h2, l3, h3;
            upk2(cc[hp][0], l0, h0);
            upk2(cc[hp][1], l1, h1);
            upk2(cc[hp][2], l2, h2);
            upk2(cc[hp][3], l3, h3);
            red4[(tp * 8 + 2 * hp) * 64 + dq]     = make_float4(l0, l1, l2, l3);
            red4[(tp * 8 + 2 * hp + 1) * 64 + dq] = make_float4(h0, h1, h2, h3);
        }
    }
    if (tid < 8) sL[tid] = 1.0f / sL[tid];
    __syncthreads();

    float* ctx_s = sP;                  // [8][260]
    for (int i = tid; i < 2048; i += 256) {
        int hh = i >> 8, k = i & 255;
        float v = xsf[(0 * 8 + hh) * 256 + k] + xsf[(1 * 8 + hh) * 256 + k]
                + xsf[(2 * 8 + hh) * 256 + k] + xsf[(3 * 8 + hh) * 256 + k];
        ctx_s[hh * 260 + k] = v * sL[hh];
    }
    __syncthreads();

    {
        float a0 = 0.f, a1 = 0.f;
        const float* ch = ctx_s + w * 260;
        #pragma unroll 4
        for (int k = 0; k < 256; ++k) {
            float2 wv = *reinterpret_cast<const float2*>(
                &Wv[(size_t)k * D_ + w * 64 + lane * 2]);
            float cv = ch[k];
            a0 += cv * wv.x; a1 += cv * wv.y;
        }
        slot[w * 64 + lane * 2]     = a0;
        slot[w * 64 + lane * 2 + 1] = a1;
    }
}

// ---------------------------------------------------------------------------
// K5 (cp.async, unchanged): out = o @ Wo, in-place.  64 blocks x 4 rows.
#define K5_SMEM_FLOATS 20480
#define K5_SMEM_BYTES  (K5_SMEM_FLOATS * 4)

__global__ __launch_bounds__(256) void nsca14_k5_oproj(
    const float* __restrict__ Wo,
    float* __restrict__ dout)
{
    extern __shared__ float s5[];
    float*  os   = s5;                          // [4][512]
    float4* red4 = (float4*)(s5 + 18432);       // [4][128] f4

    int r0 = blockIdx.x * 4;
    int tid = threadIdx.x;
    int ks = tid >> 7;
    int ch = tid & 127;

    {
        const float4* src = (const float4*)(dout + (size_t)r0 * 512);
        float4* os4 = (float4*)os;
        os4[tid]       = src[tid];
        os4[tid + 256] = src[tid + 256];
    }

    const float4* Wo4 = (const float4*)Wo;
    uint32_t b0addr = (uint32_t)__cvta_generic_to_shared(s5 + 2048);
    uint32_t b1addr = b0addr + 8192 * 4;

    {
        #pragma unroll
        for (int j = 0; j < 8; ++j) {
            int e = tid + j * 256;
            asm volatile("cp.async.cg.shared.global [%0], [%1], 16;"
                :: "r"(b0addr + e * 16), "l"(Wo4 + e) : "memory");
        }
        asm volatile("cp.async.commit_group;" ::: "memory");
    }

    float4 a0 = {0,0,0,0}, a1 = {0,0,0,0}, a2 = {0,0,0,0}, a3 = {0,0,0,0};

    for (int c = 0; c < 32; ++c) {
        if (c + 1 < 32) {
            uint32_t dst = ((c + 1) & 1) ? b1addr : b0addr;
            const float4* g = Wo4 + (size_t)(c + 1) * 2048;
            #pragma unroll
            for (int j = 0; j < 8; ++j) {
                int e = tid + j * 256;
                asm volatile("cp.async.cg.shared.global [%0], [%1], 16;"
                    :: "r"(dst + e * 16), "l"(g + e) : "memory");
            }
            asm volatile("cp.async.commit_group;" ::: "memory");
            asm volatile("cp.async.wait_group 1;" ::: "memory");
        } else {
            asm volatile("cp.async.wait_group 0;" ::: "memory");
        }
        __syncthreads();

        const float4* Bc = (const float4*)(s5 + 2048 + (c & 1) * 8192);
        #pragma unroll
        for (int j = 0; j < 8; ++j) {
            int kl = ks + 2 * j;
            int k  = c * 16 + kl;
            float4 wv = Bc[kl * 128 + ch];
            float o0 = os[k], o1 = os[512 + k], o2 = os[1024 + k], o3 = os[1536 + k];
            a0.x += o0 * wv.x; a0.y += o0 * wv.y; a0.z += o0 * wv.z; a0.w += o0 * wv.w;
            a1.x += o1 * wv.x; a1.y += o1 * wv.y; a1.z += o1 * wv.z; a1.w += o1 * wv.w;
            a2.x += o2 * wv.x; a2.y += o2 * wv.y; a2.z += o2 * wv.z; a2.w += o2 * wv.w;
            a3.x += o3 * wv.x; a3.y += o3 * wv.y; a3.z += o3 * wv.z; a3.w += o3 * wv.w;
        }
        __syncthreads();
    }

    if (ks == 1) {
        red4[0 * 128 + ch] = a0;
        red4[1 * 128 + ch] = a1;
        red4[2 * 128 + ch] = a2;
        red4[3 * 128 + ch] = a3;
    }
    __syncthreads();
    if (ks == 0) {
        float4 b0 = red4[0 * 128 + ch];
        float4 b1 = red4[1 * 128 + ch];
        float4 b2 = red4[2 * 128 + ch];
        float4 b3 = red4[3 * 128 + ch];
        a0.x += b0.x; a0.y += b0.y; a0.z += b0.z; a0.w += b0.w;
        a1.x += b1.x; a1.y += b1.y; a1.z += b1.z; a1.w += b1.w;
        a2.x += b2.x; a2.y += b2.y; a2.z += b2.z; a2.w += b2.w;
        a3.x += b3.x; a3.y += b3.y; a3.z += b3.z; a3.w += b3.w;
        float4* out4 = (float4*)dout;
        out4[(size_t)(r0 + 0) * 128 + ch] = a0;
        out4[(size_t)(r0 + 1) * 128 + ch] = a1;
        out4[(size_t)(r0 + 2) * 128 + ch] = a2;
        out4[(size_t)(r0 + 3) * 128 + ch] = a3;
    }
}

// ---------------------------------------------------------------------------
extern "C" void kernel_launch(void* const* d_in, const int* in_sizes, int n_in,
                              void* d_out, int out_size)
{
    const float* latents = (const float*)d_in[0];
    const float* bytes   = (const float*)d_in[1];
    const float* rqw     = (const float*)d_in[2];
    const float* rqb     = (const float*)d_in[3];
    const float* rkw     = (const float*)d_in[4];
    const float* rkb     = (const float*)d_in[5];
    const float* Wq      = (const float*)d_in[6];
    const float* Wk      = (const float*)d_in[7];
    const float* Wv      = (const float*)d_in[8];
    const float* Wo      = (const float*)d_in[9];
    float* out = (float*)d_out;

    cudaFuncSetAttribute(nsca14_k4_attn,
                         cudaFuncAttributeMaxDynamicSharedMemorySize, NS14_SMEM_BYTES);
    cudaFuncSetAttribute(nsca14_k5_oproj,
                         cudaFuncAttributeMaxDynamicSharedMemorySize, K5_SMEM_BYTES);

    nsca14_k1_summary<<<B_ * NB, 256>>>(bytes, rkw, rkb, out);
    nsca14_k2_topk<<<NLAT, 256>>>(latents, rqw, rqb, out);
    nsca14_k4_attn<<<NLAT, 256, NS14_SMEM_BYTES>>>(bytes, latents, Wq, Wk, Wv, out);
    nsca14_k5_oproj<<<64, 256, K5_SMEM_BYTES>>>(Wo, out);
}